// round 3
// baseline (speedup 1.0000x reference)
#include <cuda_runtime.h>

// FilterLayer: y[b,c,h,w] = sum_{i,j in 5x5} x_pad[b,c,h+i,w+j] * f[b,i*5+j,h,w]
// B=4, C=3, H=W=512, window=5, zero pad 2.
// R3: 4 pixels/thread, all global traffic in 128-bit transactions.
//   f: 25x LDG.128 streaming (__ldcs) per thread (dominant 105MB stream)
//   x: staged in smem; per (c,row) two aligned conflict-free LDS.128
//   out: 3x STG.128

#define IMG_H 512
#define IMG_W 512
#define TWX 32          // threads in x
#define TH  8           // threads in y (= rows per tile)
#define PX  4           // pixels per thread (horizontal)
#define TILE_W (TWX * PX)        // 128 pixels wide
#define HALO 2
#define TILE_R (TH + 2 * HALO)   // 12
#define TILE_C (TILE_W + 4)      // 132 cols (taps reach p+4, max 131)

__global__ __launch_bounds__(256, 4)
void filter_layer_kernel(const float* __restrict__ x,
                         const float* __restrict__ f,
                         float* __restrict__ out)
{
    __shared__ __align__(16) float xs[3][TILE_R][TILE_C];

    const int b  = blockIdx.z;
    const int w0 = blockIdx.x * TILE_W;
    const int h0 = blockIdx.y * TH;
    const int tx = threadIdx.x;
    const int ty = threadIdx.y;
    const int tid = ty * TWX + tx;

    const int HW  = IMG_H * IMG_W;
    const int W4  = IMG_W / 4;
    const int HW4 = HW / 4;

    // ---- Stage 3-channel x tile with halo (zero-padded at borders) ----
    // tile col t <-> global col w0 + t - HALO
    const float* xb = x + (size_t)b * 3 * HW;
    for (int idx = tid; idx < 3 * TILE_R * TILE_C; idx += 256) {
        int c   = idx / (TILE_R * TILE_C);
        int rem = idx - c * (TILE_R * TILE_C);
        int r   = rem / TILE_C;
        int col = rem - r * TILE_C;
        int gr  = h0 + r - HALO;
        int gc  = w0 + col - HALO;
        float v = 0.0f;
        if ((unsigned)gr < (unsigned)IMG_H && (unsigned)gc < (unsigned)IMG_W)
            v = __ldg(xb + c * HW + gr * IMG_W + gc);
        xs[c][r][col] = v;
    }
    __syncthreads();

    // ---- 4 pixels per thread: base pixel p0 = 4*tx ----
    const int h  = h0 + ty;
    const int p0 = 4 * tx;                      // local pixel col
    // f as float4: base index for (h, w0 + p0)
    const float4* f4 = (const float4*)(f + (size_t)b * 25 * HW);
    const int fbase = h * W4 + (w0 >> 2) + tx;

    float4 a0 = make_float4(0.f, 0.f, 0.f, 0.f);
    float4 a1 = a0, a2 = a0;

    #pragma unroll
    for (int i = 0; i < 5; ++i) {
        // load 8 consecutive smem floats per channel, 16B-aligned at col p0
        float xr0[8], xr1[8], xr2[8];
        {
            const float4* r0 = (const float4*)&xs[0][ty + i][p0];
            const float4* r1 = (const float4*)&xs[1][ty + i][p0];
            const float4* r2 = (const float4*)&xs[2][ty + i][p0];
            float4 u, v;
            u = r0[0]; v = r0[1];
            xr0[0]=u.x; xr0[1]=u.y; xr0[2]=u.z; xr0[3]=u.w;
            xr0[4]=v.x; xr0[5]=v.y; xr0[6]=v.z; xr0[7]=v.w;
            u = r1[0]; v = r1[1];
            xr1[0]=u.x; xr1[1]=u.y; xr1[2]=u.z; xr1[3]=u.w;
            xr1[4]=v.x; xr1[5]=v.y; xr1[6]=v.z; xr1[7]=v.w;
            u = r2[0]; v = r2[1];
            xr2[0]=u.x; xr2[1]=u.y; xr2[2]=u.z; xr2[3]=u.w;
            xr2[4]=v.x; xr2[5]=v.y; xr2[6]=v.z; xr2[7]=v.w;
        }
        #pragma unroll
        for (int j = 0; j < 5; ++j) {
            const int k = i * 5 + j;
            const float4 fv = __ldcs(f4 + (size_t)k * HW4 + fbase);
            a0.x = fmaf(xr0[j    ], fv.x, a0.x);
            a0.y = fmaf(xr0[j + 1], fv.y, a0.y);
            a0.z = fmaf(xr0[j + 2], fv.z, a0.z);
            a0.w = fmaf(xr0[j + 3], fv.w, a0.w);
            a1.x = fmaf(xr1[j    ], fv.x, a1.x);
            a1.y = fmaf(xr1[j + 1], fv.y, a1.y);
            a1.z = fmaf(xr1[j + 2], fv.z, a1.z);
            a1.w = fmaf(xr1[j + 3], fv.w, a1.w);
            a2.x = fmaf(xr2[j    ], fv.x, a2.x);
            a2.y = fmaf(xr2[j + 1], fv.y, a2.y);
            a2.z = fmaf(xr2[j + 2], fv.z, a2.z);
            a2.w = fmaf(xr2[j + 3], fv.w, a2.w);
        }
    }

    float4* o4 = (float4*)(out + (size_t)b * 3 * HW);
    const int obase = h * W4 + (w0 >> 2) + tx;
    o4[obase]            = a0;
    o4[obase + HW4]      = a1;
    o4[obase + 2 * HW4]  = a2;
}

extern "C" void kernel_launch(void* const* d_in, const int* in_sizes, int n_in,
                              void* d_out, int out_size)
{
    const float* x = (const float*)d_in[0];
    const float* f = (const float*)d_in[1];
    float* out = (float*)d_out;

    dim3 block(TWX, TH, 1);                        // 256 threads
    dim3 grid(IMG_W / TILE_W, IMG_H / TH, 4);      // 4 x 64 x 4 = 1024 blocks
    filter_layer_kernel<<<grid, block>>>(x, f, out);
}

// round 4
// speedup vs baseline: 1.3957x; 1.3957x over previous
#include <cuda_runtime.h>

// FilterLayer: y[b,c,h,w] = sum_{i,j in 5x5} x_pad[b,c,h+i,w+j] * f[b,i*5+j,h,w]
// B=4, C=3, H=W=512, window=5, zero pad 2.
// R4: 2 pixels/thread, 64-bit accesses. Middle ground between R2 (scalar,
// issue-heavy) and R3 (float4, register-bound). Per thread:
//   f: 25x LDG.64 streaming (__ldcs), x: 45x LDS.64 (conflict-free),
//   out: 3x STG.64. ~40 regs -> high occupancy, HBM should bind.

#define IMG_H 512
#define IMG_W 512
#define TWX 32
#define TH  8
#define PX  2
#define TILE_W (TWX * PX)        // 64
#define HALO 2
#define TILE_R (TH + 2 * HALO)   // 12
#define TILE_C (TILE_W + 4)      // 68 (taps reach p0+5, max 67)

__global__ void filter_layer_kernel(const float* __restrict__ x,
                                    const float* __restrict__ f,
                                    float* __restrict__ out)
{
    __shared__ __align__(8) float xs[3][TILE_R][TILE_C];

    const int b  = blockIdx.z;
    const int w0 = blockIdx.x * TILE_W;
    const int h0 = blockIdx.y * TH;
    const int tx = threadIdx.x;
    const int ty = threadIdx.y;
    const int tid = ty * TWX + tx;

    const int HW  = IMG_H * IMG_W;
    const int W2  = IMG_W / 2;
    const int HW2 = HW / 2;

    // ---- Stage 3-channel x tile with halo (zero-padded at borders) ----
    const float* xb = x + (size_t)b * 3 * HW;
    for (int idx = tid; idx < 3 * TILE_R * TILE_C; idx += 256) {
        int c   = idx / (TILE_R * TILE_C);
        int rem = idx - c * (TILE_R * TILE_C);
        int r   = rem / TILE_C;
        int col = rem - r * TILE_C;
        int gr  = h0 + r - HALO;
        int gc  = w0 + col - HALO;
        float v = 0.0f;
        if ((unsigned)gr < (unsigned)IMG_H && (unsigned)gc < (unsigned)IMG_W)
            v = __ldg(xb + c * HW + gr * IMG_W + gc);
        xs[c][r][col] = v;
    }
    __syncthreads();

    // ---- 2 pixels per thread: local cols p0, p0+1 ----
    const int h  = h0 + ty;
    const int p0 = 2 * tx;
    const float2* f2 = (const float2*)(f + (size_t)b * 25 * HW);
    const int fbase = h * W2 + (w0 >> 1) + tx;

    float2 a0 = make_float2(0.f, 0.f);
    float2 a1 = a0, a2 = a0;

    #pragma unroll
    for (int i = 0; i < 5; ++i) {
        // 6 consecutive smem floats per channel, 8B-aligned at col p0:
        // three LDS.64 each -> conflict-free
        float xr0[6], xr1[6], xr2[6];
        {
            const float2* r0 = (const float2*)&xs[0][ty + i][p0];
            const float2* r1 = (const float2*)&xs[1][ty + i][p0];
            const float2* r2 = (const float2*)&xs[2][ty + i][p0];
            float2 u;
            u = r0[0]; xr0[0]=u.x; xr0[1]=u.y;
            u = r0[1]; xr0[2]=u.x; xr0[3]=u.y;
            u = r0[2]; xr0[4]=u.x; xr0[5]=u.y;
            u = r1[0]; xr1[0]=u.x; xr1[1]=u.y;
            u = r1[1]; xr1[2]=u.x; xr1[3]=u.y;
            u = r1[2]; xr1[4]=u.x; xr1[5]=u.y;
            u = r2[0]; xr2[0]=u.x; xr2[1]=u.y;
            u = r2[1]; xr2[2]=u.x; xr2[3]=u.y;
            u = r2[2]; xr2[4]=u.x; xr2[5]=u.y;
        }
        #pragma unroll
        for (int j = 0; j < 5; ++j) {
            const int k = i * 5 + j;
            const float2 fv = __ldcs(f2 + (size_t)k * HW2 + fbase);
            a0.x = fmaf(xr0[j    ], fv.x, a0.x);
            a0.y = fmaf(xr0[j + 1], fv.y, a0.y);
            a1.x = fmaf(xr1[j    ], fv.x, a1.x);
            a1.y = fmaf(xr1[j + 1], fv.y, a1.y);
            a2.x = fmaf(xr2[j    ], fv.x, a2.x);
            a2.y = fmaf(xr2[j + 1], fv.y, a2.y);
        }
    }

    float2* o2 = (float2*)(out + (size_t)b * 3 * HW);
    const int obase = h * W2 + (w0 >> 1) + tx;
    o2[obase]           = a0;
    o2[obase + HW2]     = a1;
    o2[obase + 2 * HW2] = a2;
}

extern "C" void kernel_launch(void* const* d_in, const int* in_sizes, int n_in,
                              void* d_out, int out_size)
{
    const float* x = (const float*)d_in[0];
    const float* f = (const float*)d_in[1];
    float* out = (float*)d_out;

    dim3 block(TWX, TH, 1);                        // 256 threads
    dim3 grid(IMG_W / TILE_W, IMG_H / TH, 4);      // 8 x 64 x 4 = 2048 blocks
    filter_layer_kernel<<<grid, block>>>(x, f, out);
}